// round 2
// baseline (speedup 1.0000x reference)
#include <cuda_runtime.h>
#include <cuda_fp16.h>
#include <mma.h>

using namespace nvcuda;

#define NOBJ 1024
#define IB   128      // actee (i) block per CTA
#define JB   128      // actor (j) chunk per CTA
#define DP   64       // padded hidden dim (50 -> 64)
#define TPB  256

// partial[m][jc][i][50]  (fully overwritten every launch by the 512 CTAs)
__device__ float g_partial[8 * 8 * NOBJ * 50];

static constexpr int SMEM_BYTES =
    (4 * DP * DP + 2 * IB * DP) * 2    /* W1hi/lo, W2hi/lo, Hhi, Hlo (half) */
  + (IB * DP) * 4                      /* Ct (float) */
  + (5 * 64 + IB + JB) * 4;            /* p,q,r,b1,b2,beta,alpha */

// C(rows warp*16..+16) = A_hi@B_hi + A_hi@B_lo + A_lo@B_hi   (fp32 accum)
__device__ __forceinline__ void gemm64_split(const half* __restrict__ Ahi,
                                             const half* __restrict__ Alo,
                                             const half* __restrict__ Bhi,
                                             const half* __restrict__ Blo,
                                             float* __restrict__ C, int warp)
{
    wmma::fragment<wmma::matrix_a, 16, 16, 16, half, wmma::row_major> ahi[4], alo[4];
#pragma unroll
    for (int kt = 0; kt < 4; kt++) {
        wmma::load_matrix_sync(ahi[kt], Ahi + (warp * 16) * DP + kt * 16, DP);
        wmma::load_matrix_sync(alo[kt], Alo + (warp * 16) * DP + kt * 16, DP);
    }
#pragma unroll
    for (int nt = 0; nt < 4; nt++) {
        wmma::fragment<wmma::accumulator, 16, 16, 16, float> c;
        wmma::fill_fragment(c, 0.0f);
#pragma unroll
        for (int kt = 0; kt < 4; kt++) {
            wmma::fragment<wmma::matrix_b, 16, 16, 16, half, wmma::row_major> bhi, blo;
            wmma::load_matrix_sync(bhi, Bhi + (kt * 16) * DP + nt * 16, DP);
            wmma::load_matrix_sync(blo, Blo + (kt * 16) * DP + nt * 16, DP);
            wmma::mma_sync(c, ahi[kt], bhi, c);
            wmma::mma_sync(c, ahi[kt], blo, c);
            wmma::mma_sync(c, alo[kt], bhi, c);
        }
        wmma::store_matrix_sync(C + (warp * 16) * DP + nt * 16, c, DP,
                                wmma::mem_row_major);
    }
}

__device__ __forceinline__ void split_hl(float v, half& hi, half& lo)
{
    hi = __float2half_rn(v);
    lo = __float2half_rn(v - __half2float(hi));
}

__global__ void __launch_bounds__(TPB, 2)
pair_kernel(const float* __restrict__ obj0, const float* __restrict__ obj1,
            const float* __restrict__ prev0, const float* __restrict__ prev1,
            const float* __restrict__ gW0, const float* __restrict__ gb0,
            const float* __restrict__ gW1, const float* __restrict__ gb1,
            const float* __restrict__ gW2, const float* __restrict__ gb2)
{
    const int m  = blockIdx.x;   // module 0..7  (actor = m>>1, actee class = m&1)
    const int ib = blockIdx.y;   // i-block 0..7
    const int jc = blockIdx.z;   // j-chunk 0..7
    const int t  = threadIdx.x;
    const int warp = t >> 5;

    const int ac = m >> 1;
    const float* actor = (ac == 0) ? obj0 : (ac == 1) ? obj1 : (ac == 2) ? prev0 : prev1;
    const float* actee = (m & 1) ? obj1 : obj0;

    extern __shared__ char smem_raw[];
    half*  W1hi = (half*)smem_raw;           // [64][64], zero padded
    half*  W1lo = W1hi + DP * DP;
    half*  W2hi = W1lo + DP * DP;
    half*  W2lo = W2hi + DP * DP;
    half*  Hhi  = W2lo + DP * DP;            // [128][64]
    half*  Hlo  = Hhi + IB * DP;             // [128][64]
    float* Ct   = (float*)(Hlo + IB * DP);   // [128][64] fp32 GEMM out
    float* p_   = Ct + IB * DP;              // 64
    float* q_   = p_ + 64;
    float* r_   = q_ + 64;
    float* b1_  = r_ + 64;
    float* b2_  = b1_ + 64;
    float* beta = b2_ + 64;                  // 128 actee values
    float* alph = beta + IB;                 // 128 actor values

    // ---- stage weights / vectors (zero padded to 64) ----
    for (int x = t; x < DP * DP; x += TPB) {
        W1hi[x] = __float2half(0.f);  W1lo[x] = __float2half(0.f);
        W2hi[x] = __float2half(0.f);  W2lo[x] = __float2half(0.f);
    }
    if (t < 64) {
        p_[t]  = (t < 50) ? gW0[m * 100 + t]      : 0.f;   // W0[m][0][t]
        q_[t]  = (t < 50) ? gW0[m * 100 + 50 + t] : 0.f;   // W0[m][1][t]
        r_[t]  = (t < 50) ? gb0[m * 50 + t]       : 0.f;
        b1_[t] = (t < 50) ? gb1[m * 50 + t]       : 0.f;
        b2_[t] = (t < 50) ? gb2[m * 50 + t]       : 0.f;
    }
    if (t < IB) {
        beta[t] = actee[ib * IB + t];
        alph[t] = actor[jc * JB + t];
    }
    __syncthreads();
    for (int x = t; x < 2500; x += TPB) {
        int k = x / 50, l = x % 50;
        half hi, lo;
        split_hl(gW1[m * 2500 + x], hi, lo);
        W1hi[k * DP + l] = hi;  W1lo[k * DP + l] = lo;
        split_hl(gW2[m * 2500 + x], hi, lo);
        W2hi[k * DP + l] = hi;  W2lo[k * DP + l] = lo;
    }
    __syncthreads();

    // Fa accumulator in registers: thread t owns x = t + k*TPB, k=0..31
    float Freg[32];
#pragma unroll
    for (int k = 0; k < 32; k++) Freg[k] = 0.f;

    // ---- main loop over actors j in this chunk ----
    for (int jj = 0; jj < JB; ++jj) {
        const float alpha = alph[jj];
        // H1[i][k] = relu(alpha*p[k] + beta[i]*q[k] + r[k])  (layer-1 collapse)
        for (int x = t; x < IB * DP; x += TPB) {
            int pi = x >> 6, k = x & 63;
            float v = fmaf(alpha, p_[k], fmaf(beta[pi], q_[k], r_[k]));
            v = fmaxf(v, 0.f);
            half hi, lo; split_hl(v, hi, lo);
            Hhi[x] = hi;  Hlo[x] = lo;
        }
        __syncthreads();

        gemm64_split(Hhi, Hlo, W1hi, W1lo, Ct, warp);      // z2 = H1 @ W1
        __syncthreads();

        for (int x = t; x < IB * DP; x += TPB) {
            float v = fmaxf(Ct[x] + b1_[x & 63], 0.f);     // H2
            half hi, lo; split_hl(v, hi, lo);
            Hhi[x] = hi;  Hlo[x] = lo;
        }
        __syncthreads();

        gemm64_split(Hhi, Hlo, W2hi, W2lo, Ct, warp);      // z3 = H2 @ W2
        __syncthreads();

#pragma unroll
        for (int k = 0; k < 32; k++) {
            int x = k * TPB + t;
            Freg[k] += fmaxf(Ct[x] + b2_[x & 63], 0.f);    // sum_j h3
        }
        __syncthreads();
    }

    // ---- write deterministic partials (W3 folded post-sum in finalize) ----
#pragma unroll
    for (int k = 0; k < 32; k++) {
        int x = k * TPB + t;
        int pi = x >> 6, col = x & 63;
        if (col < 50)
            g_partial[((m * 8 + jc) * NOBJ + ib * IB + pi) * 50 + col] = Freg[k];
    }
}

__global__ void finalize_kernel(const float* __restrict__ gW3,
                                const float* __restrict__ gb3,
                                const float* __restrict__ aW0,
                                const float* __restrict__ ab0,
                                const float* __restrict__ aW1,
                                const float* __restrict__ ab1,
                                float* __restrict__ out)
{
    int t = blockIdx.x * blockDim.x + threadIdx.x;   // 0..2047
    if (t >= 2048) return;
    const int c = t >> 10;       // actee class
    const int i = t & 1023;      // object index

    float F[20];
#pragma unroll
    for (int o = 0; o < 20; o++) F[o] = 0.f;

    for (int a = 0; a < 4; a++) {
        const int m = a * 2 + c;
        for (int k = 0; k < 50; k++) {
            float s = 0.f;
#pragma unroll
            for (int jcc = 0; jcc < 8; jcc++)
                s += g_partial[((m * 8 + jcc) * NOBJ + i) * 50 + k];
            const float* w3 = gW3 + m * 1000 + k * 20;   // gW3[m][k][:]
#pragma unroll
            for (int o = 0; o < 20; o++) F[o] = fmaf(s, w3[o], F[o]);
        }
#pragma unroll
        for (int o = 0; o < 20; o++) F[o] += 1024.f * gb3[m * 20 + o];
    }

    // apply_force MLP: 20 -> 50 (relu) -> 1
    float pred = ab1[c];
    for (int l = 0; l < 50; l++) {
        float h = ab0[c * 50 + l];
#pragma unroll
        for (int o = 0; o < 20; o++)
            h = fmaf(F[o], aW0[c * 1000 + o * 50 + l], h);
        h = fmaxf(h, 0.f);
        pred = fmaf(h, aW1[c * 50 + l], pred);
    }
    out[c * 1024 + i] = pred;
}

extern "C" void kernel_launch(void* const* d_in, const int* in_sizes, int n_in,
                              void* d_out, int out_size)
{
    const float* obj0  = (const float*)d_in[0];
    const float* obj1  = (const float*)d_in[1];
    const float* prev0 = (const float*)d_in[2];
    const float* prev1 = (const float*)d_in[3];
    const float* gW0   = (const float*)d_in[4];
    const float* gb0   = (const float*)d_in[5];
    const float* gW1   = (const float*)d_in[6];
    const float* gb1   = (const float*)d_in[7];
    const float* gW2   = (const float*)d_in[8];
    const float* gb2   = (const float*)d_in[9];
    const float* gW3   = (const float*)d_in[10];
    const float* gb3   = (const float*)d_in[11];
    const float* aW0   = (const float*)d_in[12];
    const float* ab0   = (const float*)d_in[13];
    const float* aW1   = (const float*)d_in[14];
    const float* ab1   = (const float*)d_in[15];

    cudaFuncSetAttribute(pair_kernel,
                         cudaFuncAttributeMaxDynamicSharedMemorySize, SMEM_BYTES);

    dim3 grid(8, 8, 8);   // (module, i-block, j-chunk)
    pair_kernel<<<grid, TPB, SMEM_BYTES>>>(obj0, obj1, prev0, prev1,
                                           gW0, gb0, gW1, gb1, gW2, gb2);
    finalize_kernel<<<8, 256>>>(gW3, gb3, aW0, ab0, aW1, ab1, (float*)d_out);
}

// round 3
// speedup vs baseline: 5.5266x; 5.5266x over previous
#include <cuda_runtime.h>
#include <cuda_fp16.h>
#include <cstdint>

#define NOBJ 1024
#define TPB  256
#define WST  72        // SMEM weight row stride (halfs): 144B -> conflict-free

// partial[m][jc][i][50]  (fully overwritten every launch by the 512 CTAs)
__device__ float g_partial[8 * 8 * NOBJ * 50];

// ---------------------------------------------------------------------------
// mma.m16n8k16 row.col f32.f16.f16.f32
// A frag (4 b32): a0=(row g, k=2t4,2t4+1) a1=(g+8, same) a2=(g, +8) a3=(g+8, +8)
// B frag (2 b32): b0=(k=2t4,2t4+1, n=g)   b1=(k=+8, n=g)
// C frag (4 f32): c0=(g, n=2t4) c1=(g, 2t4+1) c2=(g+8, 2t4) c3=(g+8, 2t4+1)
// ---------------------------------------------------------------------------
__device__ __forceinline__ void mma16816(float c[4], const uint32_t a[4],
                                         uint32_t b0, uint32_t b1)
{
    asm("mma.sync.aligned.m16n8k16.row.col.f32.f16.f16.f32 "
        "{%0,%1,%2,%3}, {%4,%5,%6,%7}, {%8,%9}, {%0,%1,%2,%3};\n"
        : "+f"(c[0]), "+f"(c[1]), "+f"(c[2]), "+f"(c[3])
        : "r"(a[0]), "r"(a[1]), "r"(a[2]), "r"(a[3]), "r"(b0), "r"(b1));
}

// split (x,y) into fp16 hi pair + fp16 lo (residual) pair, packed as b32
__device__ __forceinline__ void split2(float x, float y, uint32_t& hi, uint32_t& lo)
{
    half2 h = __floats2half2_rn(x, y);
    float2 f = __half22float2(h);
    half2 l = __floats2half2_rn(x - f.x, y - f.y);
    hi = *reinterpret_cast<uint32_t*>(&h);
    lo = *reinterpret_cast<uint32_t*>(&l);
}

__device__ __forceinline__ void split_w(float v, half& hi, half& lo)
{
    hi = __float2half_rn(v);
    lo = __float2half_rn(v - __half2float(hi));
}

__global__ void __launch_bounds__(TPB, 1)
pair_kernel(const float* __restrict__ obj0, const float* __restrict__ obj1,
            const float* __restrict__ prev0, const float* __restrict__ prev1,
            const float* __restrict__ gW0, const float* __restrict__ gb0,
            const float* __restrict__ gW1, const float* __restrict__ gb1,
            const float* __restrict__ gW2, const float* __restrict__ gb2)
{
    const int m  = blockIdx.x;   // module (actor class = m>>1, actee class = m&1)
    const int ib = blockIdx.y;   // i-block (128 actees)
    const int jc = blockIdx.z;   // j-chunk (128 actors)
    const int t  = threadIdx.x;
    const int w  = t >> 5;
    const int lane = t & 31;
    const int t4 = lane & 3;
    const int g  = lane >> 2;

    const int ac = m >> 1;
    const float* actor = (ac == 0) ? obj0 : (ac == 1) ? obj1 : (ac == 2) ? prev0 : prev1;
    const float* actee = (m & 1) ? obj1 : obj0;

    // Transposed, padded weights: Wt[n][k] = W[k][n]; row 50 of W carries bias.
    __shared__ half Wt1hi[64 * WST], Wt1lo[64 * WST];
    __shared__ half Wt2hi[64 * WST], Wt2lo[64 * WST];
    __shared__ float alph[128];

    for (int x = t; x < 64 * WST; x += TPB) {
        Wt1hi[x] = __float2half(0.f);  Wt1lo[x] = __float2half(0.f);
        Wt2hi[x] = __float2half(0.f);  Wt2lo[x] = __float2half(0.f);
    }
    __syncthreads();
    for (int x = t; x < 51 * 50; x += TPB) {
        int k = x / 50, n = x % 50;
        float w1 = (k < 50) ? gW1[m * 2500 + k * 50 + n] : gb1[m * 50 + n];
        float w2 = (k < 50) ? gW2[m * 2500 + k * 50 + n] : gb2[m * 50 + n];
        half hi, lo;
        split_w(w1, hi, lo);  Wt1hi[n * WST + k] = hi;  Wt1lo[n * WST + k] = lo;
        split_w(w2, hi, lo);  Wt2hi[n * WST + k] = hi;  Wt2lo[n * WST + k] = lo;
    }
    if (t < 128) alph[t] = actor[jc * 128 + t];

    // per-thread layer-1 constants at this thread's 16 fragment columns
    float pc[16], qc[16], rc[16];
#pragma unroll
    for (int kt = 0; kt < 4; kt++)
#pragma unroll
        for (int s = 0; s < 4; s++) {
            int col = kt * 16 + 2 * t4 + ((s >> 1) << 3) + (s & 1);
            int idx = kt * 4 + s;
            pc[idx] = (col < 50) ? gW0[m * 100 + col] : 0.f;        // W0[m][0][col]
            qc[idx] = (col < 50) ? gW0[m * 100 + 50 + col] : 0.f;   // W0[m][1][col]
            rc[idx] = (col < 50) ? gb0[m * 50 + col]
                                 : (col == 50 ? 1.f : 0.f);          // bias-feed col
        }
    const float betaA = actee[ib * 128 + w * 16 + g];
    const float betaB = actee[ib * 128 + w * 16 + g + 8];

    float Fr[32];
#pragma unroll
    for (int x = 0; x < 32; x++) Fr[x] = 0.f;

    __syncthreads();    // the ONLY barrier before the writeback

    for (int jj = 0; jj < 128; ++jj) {
        const float al = alph[jj];

        // ---- layer 1 (rank-1 collapse) -> A fragments, all in registers ----
        uint32_t A2h[4][4], A2l[4][4];
#pragma unroll
        for (int kt = 0; kt < 4; kt++) {
            const int b = kt * 4;
            float u0 = fmaf(al, pc[b + 0], rc[b + 0]);
            float u1 = fmaf(al, pc[b + 1], rc[b + 1]);
            float u2 = fmaf(al, pc[b + 2], rc[b + 2]);
            float u3 = fmaf(al, pc[b + 3], rc[b + 3]);
            float vA0 = fmaxf(fmaf(betaA, qc[b + 0], u0), 0.f);
            float vA1 = fmaxf(fmaf(betaA, qc[b + 1], u1), 0.f);
            float vA2 = fmaxf(fmaf(betaA, qc[b + 2], u2), 0.f);
            float vA3 = fmaxf(fmaf(betaA, qc[b + 3], u3), 0.f);
            float vB0 = fmaxf(fmaf(betaB, qc[b + 0], u0), 0.f);
            float vB1 = fmaxf(fmaf(betaB, qc[b + 1], u1), 0.f);
            float vB2 = fmaxf(fmaf(betaB, qc[b + 2], u2), 0.f);
            float vB3 = fmaxf(fmaf(betaB, qc[b + 3], u3), 0.f);
            split2(vA0, vA1, A2h[kt][0], A2l[kt][0]);
            split2(vB0, vB1, A2h[kt][1], A2l[kt][1]);
            split2(vA2, vA3, A2h[kt][2], A2l[kt][2]);
            split2(vB2, vB3, A2h[kt][3], A2l[kt][3]);
        }

        // ---- layer 2: z2 = H1 @ W1 (+b1 via col-50 feed), chain into A3 ----
        uint32_t A3h[4][4], A3l[4][4];
#pragma unroll
        for (int nt = 0; nt < 8; nt++) {
            float c0[4] = {0.f, 0.f, 0.f, 0.f};
            float c1[4] = {0.f, 0.f, 0.f, 0.f};
            const int rowoff = (nt * 8 + g) * WST + 2 * t4;
#pragma unroll
            for (int kt = 0; kt < 4; kt++) {
                const half* ph = Wt1hi + rowoff + kt * 16;
                const half* pl = Wt1lo + rowoff + kt * 16;
                uint32_t bh0 = *(const uint32_t*)ph;
                uint32_t bh1 = *(const uint32_t*)(ph + 8);
                uint32_t bl0 = *(const uint32_t*)pl;
                uint32_t bl1 = *(const uint32_t*)(pl + 8);
                float* cc = (kt < 2) ? c0 : c1;
                mma16816(cc, A2h[kt], bh0, bh1);
                mma16816(cc, A2h[kt], bl0, bl1);
                mma16816(cc, A2l[kt], bh0, bh1);
            }
            const int col0 = nt * 8 + 2 * t4;
            float v0 = (col0 == 50) ? 1.f : fmaxf(c0[0] + c1[0], 0.f);
            float v1 = fmaxf(c0[1] + c1[1], 0.f);             // odd col, never 50
            float v2 = (col0 == 50) ? 1.f : fmaxf(c0[2] + c1[2], 0.f);
            float v3 = fmaxf(c0[3] + c1[3], 0.f);
            const int kt2 = nt >> 1, s0 = (nt & 1) ? 2 : 0;
            split2(v0, v1, A3h[kt2][s0], A3l[kt2][s0]);
            split2(v2, v3, A3h[kt2][s0 + 1], A3l[kt2][s0 + 1]);
        }

        // ---- layer 3: z3 = H2 @ W2 (+b2), relu, accumulate over j ----
#pragma unroll
        for (int nt = 0; nt < 8; nt++) {
            float c0[4] = {0.f, 0.f, 0.f, 0.f};
            float c1[4] = {0.f, 0.f, 0.f, 0.f};
            const int rowoff = (nt * 8 + g) * WST + 2 * t4;
#pragma unroll
            for (int kt = 0; kt < 4; kt++) {
                const half* ph = Wt2hi + rowoff + kt * 16;
                const half* pl = Wt2lo + rowoff + kt * 16;
                uint32_t bh0 = *(const uint32_t*)ph;
                uint32_t bh1 = *(const uint32_t*)(ph + 8);
                uint32_t bl0 = *(const uint32_t*)pl;
                uint32_t bl1 = *(const uint32_t*)(pl + 8);
                float* cc = (kt < 2) ? c0 : c1;
                mma16816(cc, A3h[kt], bh0, bh1);
                mma16816(cc, A3h[kt], bl0, bl1);
                mma16816(cc, A3l[kt], bh0, bh1);
            }
            Fr[nt * 4 + 0] += fmaxf(c0[0] + c1[0], 0.f);
            Fr[nt * 4 + 1] += fmaxf(c0[1] + c1[1], 0.f);
            Fr[nt * 4 + 2] += fmaxf(c0[2] + c1[2], 0.f);
            Fr[nt * 4 + 3] += fmaxf(c0[3] + c1[3], 0.f);
        }
    }

    // ---- deterministic partial writeback (W3 folded post-sum in finalize) ----
    const int i0 = ib * 128 + w * 16 + g;
    const long base = (long)(m * 8 + jc) * NOBJ;
#pragma unroll
    for (int nt = 0; nt < 8; nt++) {
        const int col0 = nt * 8 + 2 * t4;
        if (col0 < 50) {
            g_partial[(base + i0) * 50 + col0]     = Fr[nt * 4 + 0];
            g_partial[(base + i0 + 8) * 50 + col0] = Fr[nt * 4 + 2];
        }
        if (col0 + 1 < 50) {
            g_partial[(base + i0) * 50 + col0 + 1]     = Fr[nt * 4 + 1];
            g_partial[(base + i0 + 8) * 50 + col0 + 1] = Fr[nt * 4 + 3];
        }
    }
}

// warp-per-(c,i) finalize: jc-reduce, fold W3, apply head MLP
__global__ void __launch_bounds__(256)
finalize_kernel(const float* __restrict__ gW3, const float* __restrict__ gb3,
                const float* __restrict__ aW0, const float* __restrict__ ab0,
                const float* __restrict__ aW1, const float* __restrict__ ab1,
                float* __restrict__ out)
{
    const int warp = blockIdx.x * (blockDim.x >> 5) + (threadIdx.x >> 5);
    const int lane = threadIdx.x & 31;
    const int nwarp = gridDim.x * (blockDim.x >> 5);

    for (int ci = warp; ci < 2048; ci += nwarp) {
        const int c = ci >> 10;
        const int i = ci & 1023;

        float F[20];
#pragma unroll
        for (int o = 0; o < 20; o++) F[o] = 0.f;

        for (int idx = lane; idx < 200; idx += 32) {
            const int a = idx / 50, k = idx % 50;
            const int mm = a * 2 + c;
            const float* gp = g_partial + ((long)(mm * 8) * NOBJ + i) * 50 + k;
            float s = 0.f;
#pragma unroll
            for (int jcc = 0; jcc < 8; jcc++) s += gp[(long)jcc * NOBJ * 50];
            const float* w3 = gW3 + mm * 1000 + k * 20;
#pragma unroll
            for (int o = 0; o < 20; o++) F[o] = fmaf(s, w3[o], F[o]);
        }
#pragma unroll
        for (int off = 16; off; off >>= 1)
#pragma unroll
            for (int o = 0; o < 20; o++)
                F[o] += __shfl_xor_sync(0xffffffffu, F[o], off);
#pragma unroll
        for (int o = 0; o < 20; o++) {
            float b = gb3[(0 + c) * 20 + o] + gb3[(2 + c) * 20 + o]
                    + gb3[(4 + c) * 20 + o] + gb3[(6 + c) * 20 + o];
            F[o] += 1024.f * b;
        }

        float p = 0.f;
        for (int l = lane; l < 50; l += 32) {
            float h = ab0[c * 50 + l];
#pragma unroll
            for (int o = 0; o < 20; o++)
                h = fmaf(F[o], aW0[c * 1000 + o * 50 + l], h);
            p = fmaf(fmaxf(h, 0.f), aW1[c * 50 + l], p);
        }
#pragma unroll
        for (int off = 16; off; off >>= 1)
            p += __shfl_xor_sync(0xffffffffu, p, off);
        if (lane == 0) out[c * 1024 + i] = p + ab1[c];
    }
}

extern "C" void kernel_launch(void* const* d_in, const int* in_sizes, int n_in,
                              void* d_out, int out_size)
{
    const float* obj0  = (const float*)d_in[0];
    const float* obj1  = (const float*)d_in[1];
    const float* prev0 = (const float*)d_in[2];
    const float* prev1 = (const float*)d_in[3];
    const float* gW0   = (const float*)d_in[4];
    const float* gb0   = (const float*)d_in[5];
    const float* gW1   = (const float*)d_in[6];
    const float* gb1   = (const float*)d_in[7];
    const float* gW2   = (const float*)d_in[8];
    const float* gb2   = (const float*)d_in[9];
    const float* gW3   = (const float*)d_in[10];
    const float* gb3   = (const float*)d_in[11];
    const float* aW0   = (const float*)d_in[12];
    const float* ab0   = (const float*)d_in[13];
    const float* aW1   = (const float*)d_in[14];
    const float* ab1   = (const float*)d_in[15];

    dim3 grid(8, 8, 8);   // (module, i-block, j-chunk)
    pair_kernel<<<grid, TPB>>>(obj0, obj1, prev0, prev1,
                               gW0, gb0, gW1, gb1, gW2, gb2);
    finalize_kernel<<<64, 256>>>(gW3, gb3, aW0, ab0, aW1, ab1, (float*)d_out);
}